// round 1
// baseline (speedup 1.0000x reference)
#include <cuda_runtime.h>
#include <math.h>

#define CG 128
#define CN 64
#define CS 64
#define KK 27
#define EPS 1e-5f

#define MAX_NG 60000
#define MAX_NX 200000

// -------- scratch (device globals: no allocations allowed) --------
__device__ float d_fg[MAX_NG * CN];       // g @ Wg
__device__ float d_fs[MAX_NG * CN];       // x[down_idx] @ Ws
__device__ float d_z[MAX_NG];             // pre-BN attention logit
__device__ float d_att[MAX_NG];           // sigmoid attention coeff
__device__ float d_S[MAX_NX * KK];        // per-output-voxel per-offset scalar sums
__device__ float d_colstats[4 * CN];      // [sum_g, sq_g, sum_s, sq_s]
__device__ float d_norm[4 * CN];          // [scale_g, shift_g, scale_s, shift_s]
__device__ float d_zstats[2];             // sum_z, sq_z

// -------- zero scratch that is accumulated into --------
__global__ void zero_kernel(int nS) {
    int i = blockIdx.x * blockDim.x + threadIdx.x;
    int stride = gridDim.x * blockDim.x;
    for (int e = i; e < nS; e += stride) d_S[e] = 0.f;
    if (i < 4 * CN) d_colstats[i] = 0.f;
    if (i < 2) d_zstats[i] = 0.f;
}

// -------- fg = g @ Wg  (Ng x 128 @ 128 x 64) --------
// 256 threads: 32 rows/block, 8 threads/row, 8 cols/thread. Wg staged in smem.
__global__ __launch_bounds__(256) void gemm_g_kernel(
    const float* __restrict__ g, const float* __restrict__ Wg, int Ng) {
    __shared__ float Wsm[CG * CN];  // 32 KB
    int t = threadIdx.x;
    for (int i = t; i < CG * CN; i += 256) Wsm[i] = Wg[i];
    __syncthreads();

    int lr = t >> 3;          // local row 0..31
    int c0 = (t & 7) * 8;     // column group
    int row = blockIdx.x * 32 + lr;
    if (row >= Ng) return;

    const float4* grow = (const float4*)(g + (size_t)row * CG);
    float acc[8];
#pragma unroll
    for (int i = 0; i < 8; i++) acc[i] = 0.f;

#pragma unroll 4
    for (int k4 = 0; k4 < CG / 4; k4++) {
        float4 gv = __ldg(&grow[k4]);
#pragma unroll
        for (int kk = 0; kk < 4; kk++) {
            float gk = (&gv.x)[kk];
            int k = k4 * 4 + kk;
            float4 w0 = *(const float4*)&Wsm[k * CN + c0];
            float4 w1 = *(const float4*)&Wsm[k * CN + c0 + 4];
            acc[0] = fmaf(gk, w0.x, acc[0]);
            acc[1] = fmaf(gk, w0.y, acc[1]);
            acc[2] = fmaf(gk, w0.z, acc[2]);
            acc[3] = fmaf(gk, w0.w, acc[3]);
            acc[4] = fmaf(gk, w1.x, acc[4]);
            acc[5] = fmaf(gk, w1.y, acc[5]);
            acc[6] = fmaf(gk, w1.z, acc[6]);
            acc[7] = fmaf(gk, w1.w, acc[7]);
        }
    }
    float* o = d_fg + (size_t)row * CN + c0;
    *(float4*)(o)     = make_float4(acc[0], acc[1], acc[2], acc[3]);
    *(float4*)(o + 4) = make_float4(acc[4], acc[5], acc[6], acc[7]);
}

// -------- fs = x[down_idx] @ Ws  (Ng x 64 @ 64 x 64) --------
__global__ __launch_bounds__(256) void gemm_s_kernel(
    const float* __restrict__ x, const int* __restrict__ down_idx,
    const float* __restrict__ Ws, int Ng) {
    __shared__ float Wsm[CS * CN];  // 16 KB
    __shared__ int ds[32];
    int t = threadIdx.x;
    for (int i = t; i < CS * CN; i += 256) Wsm[i] = Ws[i];
    int rbase = blockIdx.x * 32;
    if (t < 32) ds[t] = (rbase + t < Ng) ? down_idx[rbase + t] : 0;
    __syncthreads();

    int lr = t >> 3;
    int c0 = (t & 7) * 8;
    int row = rbase + lr;
    if (row >= Ng) return;

    const float4* xrow = (const float4*)(x + (size_t)ds[lr] * CS);
    float acc[8];
#pragma unroll
    for (int i = 0; i < 8; i++) acc[i] = 0.f;

#pragma unroll 4
    for (int k4 = 0; k4 < CS / 4; k4++) {
        float4 gv = __ldg(&xrow[k4]);
#pragma unroll
        for (int kk = 0; kk < 4; kk++) {
            float gk = (&gv.x)[kk];
            int k = k4 * 4 + kk;
            float4 w0 = *(const float4*)&Wsm[k * CN + c0];
            float4 w1 = *(const float4*)&Wsm[k * CN + c0 + 4];
            acc[0] = fmaf(gk, w0.x, acc[0]);
            acc[1] = fmaf(gk, w0.y, acc[1]);
            acc[2] = fmaf(gk, w0.z, acc[2]);
            acc[3] = fmaf(gk, w0.w, acc[3]);
            acc[4] = fmaf(gk, w1.x, acc[4]);
            acc[5] = fmaf(gk, w1.y, acc[5]);
            acc[6] = fmaf(gk, w1.z, acc[6]);
            acc[7] = fmaf(gk, w1.w, acc[7]);
        }
    }
    float* o = d_fs + (size_t)row * CN + c0;
    *(float4*)(o)     = make_float4(acc[0], acc[1], acc[2], acc[3]);
    *(float4*)(o + 4) = make_float4(acc[4], acc[5], acc[6], acc[7]);
}

// -------- column mean/var partial sums over fg and fs --------
__global__ __launch_bounds__(256) void colstats_kernel(int Ng) {
    int t = threadIdx.x;
    int c = t & 63;         // column
    int grp = t >> 6;       // 0..3
    float sg = 0.f, qg = 0.f, ss = 0.f, qs = 0.f;
    for (int r = blockIdx.x * 4 + grp; r < Ng; r += gridDim.x * 4) {
        float vg = d_fg[(size_t)r * CN + c];
        sg += vg; qg += vg * vg;
        float vs = d_fs[(size_t)r * CN + c];
        ss += vs; qs += vs * vs;
    }
    __shared__ float sm[4][4][CN];
    sm[0][grp][c] = sg;
    sm[1][grp][c] = qg;
    sm[2][grp][c] = ss;
    sm[3][grp][c] = qs;
    __syncthreads();
    // 256 threads = 4 arrays x 64 cols
    int a = t >> 6;
    int cc = t & 63;
    float v = sm[a][0][cc] + sm[a][1][cc] + sm[a][2][cc] + sm[a][3][cc];
    atomicAdd(&d_colstats[a * CN + cc], v);
}

// -------- fold BN into scale/shift per column --------
__global__ void finalize_norm_kernel(
    const float* __restrict__ gg, const float* __restrict__ bg,
    const float* __restrict__ gs, const float* __restrict__ bs, int Ng) {
    int t = threadIdx.x;  // 128 threads
    if (t >= 128) return;
    int c = t & 63;
    int br = t >> 6;  // 0 = gate, 1 = shortcut
    float sum = d_colstats[br * 128 + c];
    float sq  = d_colstats[br * 128 + 64 + c];
    float inv = 1.f / (float)Ng;
    float mu = sum * inv;
    float var = sq * inv - mu * mu;
    float gam = br ? gs[c] : gg[c];
    float bet = br ? bs[c] : bg[c];
    float sc = gam * rsqrtf(var + EPS);
    d_norm[br * 128 + c] = sc;
    d_norm[br * 128 + 64 + c] = bet - mu * sc;
}

// -------- per-row: z = relu(bn(fg)) + relu(bn(fs)) dotted with Wc; z-stats --------
__global__ __launch_bounds__(256) void fuse_kernel(const float* __restrict__ Wc, int Ng) {
    __shared__ float wc[CN], sgn[CN], bgn[CN], ssn[CN], bsn[CN];
    int t = threadIdx.x;
    if (t < CN) {
        wc[t] = Wc[t];
        sgn[t] = d_norm[t];
        bgn[t] = d_norm[64 + t];
        ssn[t] = d_norm[128 + t];
        bsn[t] = d_norm[192 + t];
    }
    __syncthreads();
    int wid = t >> 5, l = t & 31;
    float bsum = 0.f, bsq = 0.f;
    for (int row = blockIdx.x * 8 + wid; row < Ng; row += gridDim.x * 8) {
        int c = 2 * l;
        float2 fg = *(const float2*)&d_fg[(size_t)row * CN + c];
        float2 fs = *(const float2*)&d_fs[(size_t)row * CN + c];
        float h0 = fmaxf(fg.x * sgn[c] + bgn[c], 0.f) + fmaxf(fs.x * ssn[c] + bsn[c], 0.f);
        float h1 = fmaxf(fg.y * sgn[c + 1] + bgn[c + 1], 0.f) + fmaxf(fs.y * ssn[c + 1] + bsn[c + 1], 0.f);
        // relu(h) is identity: both terms are >= 0
        float part = h0 * wc[c] + h1 * wc[c + 1];
#pragma unroll
        for (int o = 16; o > 0; o >>= 1) part += __shfl_down_sync(0xffffffffu, part, o);
        if (l == 0) {
            d_z[row] = part;
            bsum += part;
            bsq += part * part;
        }
    }
    __shared__ float zs[8][2];
    if (l == 0) { zs[wid][0] = bsum; zs[wid][1] = bsq; }
    __syncthreads();
    if (t == 0) {
        float a = 0.f, b = 0.f;
#pragma unroll
        for (int w = 0; w < 8; w++) { a += zs[w][0]; b += zs[w][1]; }
        atomicAdd(&d_zstats[0], a);
        atomicAdd(&d_zstats[1], b);
    }
}

// -------- att = sigmoid(bn(z)) --------
__global__ void att_kernel(const float* __restrict__ gamma_c,
                           const float* __restrict__ beta_c, int Ng) {
    int i = blockIdx.x * blockDim.x + threadIdx.x;
    if (i >= Ng) return;
    float inv = 1.f / (float)Ng;
    float mu = d_zstats[0] * inv;
    float var = d_zstats[1] * inv - mu * mu;
    float rs = rsqrtf(var + EPS);
    float zz = (d_z[i] - mu) * rs * gamma_c[0] + beta_c[0];
    d_att[i] = 1.f / (1.f + expf(-zz));
}

// -------- scatter scalar att into S[Nx][27] (rank-1 trick) --------
__global__ void scatter_kernel(const int* __restrict__ pin,
                               const int* __restrict__ pout, int total, int P) {
    int e = blockIdx.x * blockDim.x + threadIdx.x;
    if (e >= total) return;
    int k = e / P;
    float a = d_att[__ldg(&pin[e])];
    atomicAdd(&d_S[(size_t)__ldg(&pout[e]) * KK + k], a);
}

// -------- out = x * (S @ W_inv + b_inv) --------
__global__ __launch_bounds__(256) void output_kernel(
    const float* __restrict__ x, const float* __restrict__ Winv,
    const float* __restrict__ binv, float* __restrict__ out, int Nx) {
    __shared__ float w[KK][CN];   // 6.75 KB
    __shared__ float bb[CN];
    int t = threadIdx.x;
    for (int i = t; i < KK * CN; i += 256) w[i / CN][i % CN] = Winv[i];
    if (t < CN) bb[t] = binv[t];
    __syncthreads();
    int wid = t >> 5, l = t & 31;
    for (int row = blockIdx.x * 8 + wid; row < Nx; row += gridDim.x * 8) {
        float sval = (l < KK) ? d_S[(size_t)row * KK + l] : 0.f;
        int c = 2 * l;
        float a0 = bb[c], a1 = bb[c + 1];
#pragma unroll
        for (int k = 0; k < KK; k++) {
            float sk = __shfl_sync(0xffffffffu, sval, k);
            float2 wk = *(const float2*)&w[k][c];
            a0 = fmaf(sk, wk.x, a0);
            a1 = fmaf(sk, wk.y, a1);
        }
        float2 xv = *(const float2*)&x[(size_t)row * CS + c];
        float2 o;
        o.x = xv.x * a0;
        o.y = xv.y * a1;
        *(float2*)&out[(size_t)row * CS + c] = o;
    }
}

extern "C" void kernel_launch(void* const* d_in, const int* in_sizes, int n_in,
                              void* d_out, int out_size) {
    const float* g        = (const float*)d_in[0];
    const float* x        = (const float*)d_in[1];
    const int*   down_idx = (const int*)d_in[2];
    const int*   pairs_in = (const int*)d_in[3];
    const int*   pairs_out= (const int*)d_in[4];
    const float* Wg       = (const float*)d_in[5];
    const float* Ws       = (const float*)d_in[6];
    const float* Wc       = (const float*)d_in[7];
    const float* W_inv    = (const float*)d_in[8];
    const float* b_inv    = (const float*)d_in[9];
    const float* gamma_g  = (const float*)d_in[10];
    const float* beta_g   = (const float*)d_in[11];
    const float* gamma_s  = (const float*)d_in[12];
    const float* beta_s   = (const float*)d_in[13];
    const float* gamma_c  = (const float*)d_in[14];
    const float* beta_c   = (const float*)d_in[15];

    int Ng = in_sizes[0] / CG;
    int Nx = in_sizes[1] / CS;
    int KP = in_sizes[3];
    int P  = KP / KK;

    zero_kernel<<<2048, 256>>>(Nx * KK);
    gemm_g_kernel<<<(Ng + 31) / 32, 256>>>(g, Wg, Ng);
    gemm_s_kernel<<<(Ng + 31) / 32, 256>>>(x, down_idx, Ws, Ng);
    colstats_kernel<<<296, 256>>>(Ng);
    finalize_norm_kernel<<<1, 128>>>(gamma_g, beta_g, gamma_s, beta_s, Ng);
    fuse_kernel<<<(Ng + 7) / 8, 256>>>(Wc, Ng);
    att_kernel<<<(Ng + 255) / 256, 256>>>(gamma_c, beta_c, Ng);
    scatter_kernel<<<(KP + 255) / 256, 256>>>(pairs_in, pairs_out, KP, P);
    output_kernel<<<(Nx + 7) / 8, 256>>>(x, W_inv, b_inv, (float*)d_out, Nx);
}

// round 2
// speedup vs baseline: 1.4718x; 1.4718x over previous
#include <cuda_runtime.h>
#include <math.h>

#define CG 128
#define CN 64
#define CS 64
#define KK 27
#define EPS 1e-5f

#define MAX_NG 60000
#define MAX_NX 200000

// -------- scratch (device globals: no allocations allowed) --------
__device__ float d_fg[MAX_NG * CN];       // g @ Wg
__device__ float d_fs[MAX_NG * CN];       // x[down_idx] @ Ws
__device__ float d_z[MAX_NG];             // pre-BN attention logit
__device__ float d_att[MAX_NG];           // sigmoid attention coeff
__device__ float d_S[MAX_NX * KK];        // per-output-voxel per-offset scalar sums
__device__ float d_colstats[4 * CN];      // [sum_g, sq_g | sum_s, sq_s]
__device__ float d_zstats[2];             // sum_z, sq_z

// -------- zero scratch that is accumulated into --------
__global__ void zero_kernel(int nS) {
    int i = blockIdx.x * blockDim.x + threadIdx.x;
    int stride = gridDim.x * blockDim.x;
    for (int e = i; e < nS; e += stride) d_S[e] = 0.f;
    if (i < 4 * CN) d_colstats[i] = 0.f;
    if (i < 2) d_zstats[i] = 0.f;
}

// ============ fg = g @ Wg  (Ng x 128 @ 128 x 64), fused column stats ============
// 256 threads/block, block tile = 128 rows x 64 cols, thread tile = 4 rows x 8 cols.
// W staged in smem (32 KB); A rows streamed from global (L1/L2 cached, broadcast
// across the 8 column-group lanes). After the k-loop each block reduces its own
// column sum/sumsq from registers and atomically adds 128 floats to d_colstats.
__global__ __launch_bounds__(256) void gemm_g_kernel(
    const float* __restrict__ g, const float* __restrict__ Wg, int Ng) {
    __shared__ float Wsm[CG * CN];  // 32 KB, later reused for stats reduction
    int t = threadIdx.x;
    for (int i = t; i < CG * CN; i += 256) Wsm[i] = Wg[i];
    __syncthreads();

    int tr = t >> 3;            // 0..31 row group
    int c0 = (t & 7) * 8;       // column group
    int r0 = blockIdx.x * 128 + tr * 4;

    float acc[4][8];
#pragma unroll
    for (int j = 0; j < 4; j++)
#pragma unroll
        for (int i = 0; i < 8; i++) acc[j][i] = 0.f;

    bool v0 = (r0 + 0) < Ng, v1 = (r0 + 1) < Ng, v2 = (r0 + 2) < Ng, v3 = (r0 + 3) < Ng;
    const float4* g0 = (const float4*)(g + (size_t)(r0 + 0) * CG);
    const float4* g1 = (const float4*)(g + (size_t)(r0 + 1) * CG);
    const float4* g2 = (const float4*)(g + (size_t)(r0 + 2) * CG);
    const float4* g3 = (const float4*)(g + (size_t)(r0 + 3) * CG);
    const float4 z4 = make_float4(0.f, 0.f, 0.f, 0.f);

#pragma unroll 2
    for (int k4 = 0; k4 < CG / 4; k4++) {
        float4 a[4];
        a[0] = v0 ? __ldg(&g0[k4]) : z4;
        a[1] = v1 ? __ldg(&g1[k4]) : z4;
        a[2] = v2 ? __ldg(&g2[k4]) : z4;
        a[3] = v3 ? __ldg(&g3[k4]) : z4;
#pragma unroll
        for (int kk = 0; kk < 4; kk++) {
            int k = k4 * 4 + kk;
            float4 w0 = *(const float4*)&Wsm[k * CN + c0];
            float4 w1 = *(const float4*)&Wsm[k * CN + c0 + 4];
#pragma unroll
            for (int j = 0; j < 4; j++) {
                float av = (&a[j].x)[kk];
                acc[j][0] = fmaf(av, w0.x, acc[j][0]);
                acc[j][1] = fmaf(av, w0.y, acc[j][1]);
                acc[j][2] = fmaf(av, w0.z, acc[j][2]);
                acc[j][3] = fmaf(av, w0.w, acc[j][3]);
                acc[j][4] = fmaf(av, w1.x, acc[j][4]);
                acc[j][5] = fmaf(av, w1.y, acc[j][5]);
                acc[j][6] = fmaf(av, w1.z, acc[j][6]);
                acc[j][7] = fmaf(av, w1.w, acc[j][7]);
            }
        }
    }

    // write outputs
#pragma unroll
    for (int j = 0; j < 4; j++) {
        if (r0 + j < Ng) {
            float* o = d_fg + (size_t)(r0 + j) * CN + c0;
            *(float4*)(o)     = make_float4(acc[j][0], acc[j][1], acc[j][2], acc[j][3]);
            *(float4*)(o + 4) = make_float4(acc[j][4], acc[j][5], acc[j][6], acc[j][7]);
        }
    }

    // ---- fused column stats (invalid rows had a=0 -> contribute 0 to sum/sq) ----
    float csum[8], csq[8];
#pragma unroll
    for (int i = 0; i < 8; i++) {
        csum[i] = acc[0][i] + acc[1][i] + acc[2][i] + acc[3][i];
        csq[i] = acc[0][i] * acc[0][i] + acc[1][i] * acc[1][i]
               + acc[2][i] * acc[2][i] + acc[3][i] * acc[3][i];
    }
    __syncthreads();                        // done reading Wsm
    float* s_sum = Wsm;                     // [32][64]
    float* s_sq  = Wsm + 2048;              // [32][64]
#pragma unroll
    for (int i = 0; i < 8; i++) {
        s_sum[tr * 64 + c0 + i] = csum[i];
        s_sq[tr * 64 + c0 + i]  = csq[i];
    }
    __syncthreads();
    int col = t & 63, seg = t >> 6;         // 4 segs x 8 rows
    float v1s = 0.f, v2s = 0.f;
#pragma unroll
    for (int r = 0; r < 8; r++) {
        v1s += s_sum[(seg * 8 + r) * 64 + col];
        v2s += s_sq[(seg * 8 + r) * 64 + col];
    }
    __syncthreads();
    s_sum[seg * 64 + col] = v1s;
    s_sq[seg * 64 + col]  = v2s;
    __syncthreads();
    if (t < 64) {
        float a = s_sum[t] + s_sum[64 + t] + s_sum[128 + t] + s_sum[192 + t];
        float b = s_sq[t]  + s_sq[64 + t]  + s_sq[128 + t]  + s_sq[192 + t];
        atomicAdd(&d_colstats[t], a);
        atomicAdd(&d_colstats[64 + t], b);
    }
}

// ============ fs = x[down_idx] @ Ws (Ng x 64 @ 64 x 64), fused column stats ============
__global__ __launch_bounds__(256) void gemm_s_kernel(
    const float* __restrict__ x, const int* __restrict__ down_idx,
    const float* __restrict__ Ws, int Ng) {
    __shared__ float Wsm[CS * CN];  // 16 KB
    __shared__ float s_red[4096];   // 16 KB for stats reduction
    __shared__ int ds[128];
    int t = threadIdx.x;
    for (int i = t; i < CS * CN; i += 256) Wsm[i] = Ws[i];
    int rbase = blockIdx.x * 128;
    if (t < 128) ds[t] = (rbase + t < Ng) ? down_idx[rbase + t] : 0;
    __syncthreads();

    int tr = t >> 3;
    int c0 = (t & 7) * 8;
    int r0 = rbase + tr * 4;

    float acc[4][8];
#pragma unroll
    for (int j = 0; j < 4; j++)
#pragma unroll
        for (int i = 0; i < 8; i++) acc[j][i] = 0.f;

    bool vld[4];
    const float4* xp[4];
#pragma unroll
    for (int j = 0; j < 4; j++) {
        vld[j] = (r0 + j) < Ng;
        xp[j] = (const float4*)(x + (size_t)ds[tr * 4 + j] * CS);
    }
    const float4 z4 = make_float4(0.f, 0.f, 0.f, 0.f);

#pragma unroll 2
    for (int k4 = 0; k4 < CS / 4; k4++) {
        float4 a[4];
#pragma unroll
        for (int j = 0; j < 4; j++) a[j] = vld[j] ? __ldg(&xp[j][k4]) : z4;
#pragma unroll
        for (int kk = 0; kk < 4; kk++) {
            int k = k4 * 4 + kk;
            float4 w0 = *(const float4*)&Wsm[k * CN + c0];
            float4 w1 = *(const float4*)&Wsm[k * CN + c0 + 4];
#pragma unroll
            for (int j = 0; j < 4; j++) {
                float av = (&a[j].x)[kk];
                acc[j][0] = fmaf(av, w0.x, acc[j][0]);
                acc[j][1] = fmaf(av, w0.y, acc[j][1]);
                acc[j][2] = fmaf(av, w0.z, acc[j][2]);
                acc[j][3] = fmaf(av, w0.w, acc[j][3]);
                acc[j][4] = fmaf(av, w1.x, acc[j][4]);
                acc[j][5] = fmaf(av, w1.y, acc[j][5]);
                acc[j][6] = fmaf(av, w1.z, acc[j][6]);
                acc[j][7] = fmaf(av, w1.w, acc[j][7]);
            }
        }
    }

#pragma unroll
    for (int j = 0; j < 4; j++) {
        if (r0 + j < Ng) {
            float* o = d_fs + (size_t)(r0 + j) * CN + c0;
            *(float4*)(o)     = make_float4(acc[j][0], acc[j][1], acc[j][2], acc[j][3]);
            *(float4*)(o + 4) = make_float4(acc[j][4], acc[j][5], acc[j][6], acc[j][7]);
        }
    }

    float csum[8], csq[8];
#pragma unroll
    for (int i = 0; i < 8; i++) {
        csum[i] = acc[0][i] + acc[1][i] + acc[2][i] + acc[3][i];
        csq[i] = acc[0][i] * acc[0][i] + acc[1][i] * acc[1][i]
               + acc[2][i] * acc[2][i] + acc[3][i] * acc[3][i];
    }
    float* s_sum = s_red;
    float* s_sq  = s_red + 2048;
#pragma unroll
    for (int i = 0; i < 8; i++) {
        s_sum[tr * 64 + c0 + i] = csum[i];
        s_sq[tr * 64 + c0 + i]  = csq[i];
    }
    __syncthreads();
    int col = t & 63, seg = t >> 6;
    float v1s = 0.f, v2s = 0.f;
#pragma unroll
    for (int r = 0; r < 8; r++) {
        v1s += s_sum[(seg * 8 + r) * 64 + col];
        v2s += s_sq[(seg * 8 + r) * 64 + col];
    }
    __syncthreads();
    s_sum[seg * 64 + col] = v1s;
    s_sq[seg * 64 + col]  = v2s;
    __syncthreads();
    if (t < 64) {
        float a = s_sum[t] + s_sum[64 + t] + s_sum[128 + t] + s_sum[192 + t];
        float b = s_sq[t]  + s_sq[64 + t]  + s_sq[128 + t]  + s_sq[192 + t];
        atomicAdd(&d_colstats[128 + t], a);
        atomicAdd(&d_colstats[192 + t], b);
    }
}

// -------- z = (relu(bn_g(fg)) + relu(bn_s(fs))) . Wc ; accumulate z stats --------
// BN fold (finalize_norm) computed in-block from d_colstats.
__global__ __launch_bounds__(256) void fuse_kernel(
    const float* __restrict__ Wc,
    const float* __restrict__ gg, const float* __restrict__ bg,
    const float* __restrict__ gs, const float* __restrict__ bs, int Ng) {
    __shared__ float wc[CN], sgn[CN], bgn[CN], ssn[CN], bsn[CN];
    int t = threadIdx.x;
    if (t < 128) {
        int c = t & 63;
        int br = t >> 6;  // 0 = gate, 1 = shortcut
        float sum = d_colstats[br * 128 + c];
        float sq  = d_colstats[br * 128 + 64 + c];
        float inv = 1.f / (float)Ng;
        float mu = sum * inv;
        float var = sq * inv - mu * mu;
        float gam = br ? gs[c] : gg[c];
        float bet = br ? bs[c] : bg[c];
        float sc = gam * rsqrtf(var + EPS);
        if (br == 0) { sgn[c] = sc; bgn[c] = bet - mu * sc; }
        else         { ssn[c] = sc; bsn[c] = bet - mu * sc; }
        if (br == 0) wc[c] = Wc[c];
    }
    __syncthreads();
    int wid = t >> 5, l = t & 31;
    float bsum = 0.f, bsq = 0.f;
    for (int row = blockIdx.x * 8 + wid; row < Ng; row += gridDim.x * 8) {
        int c = 2 * l;
        float2 fg = *(const float2*)&d_fg[(size_t)row * CN + c];
        float2 fs = *(const float2*)&d_fs[(size_t)row * CN + c];
        float h0 = fmaxf(fg.x * sgn[c] + bgn[c], 0.f) + fmaxf(fs.x * ssn[c] + bsn[c], 0.f);
        float h1 = fmaxf(fg.y * sgn[c + 1] + bgn[c + 1], 0.f) + fmaxf(fs.y * ssn[c + 1] + bsn[c + 1], 0.f);
        // relu(h0+h1 terms) is identity: both nonneg
        float part = h0 * wc[c] + h1 * wc[c + 1];
#pragma unroll
        for (int o = 16; o > 0; o >>= 1) part += __shfl_down_sync(0xffffffffu, part, o);
        if (l == 0) {
            d_z[row] = part;
            bsum += part;
            bsq += part * part;
        }
    }
    __shared__ float zs[8][2];
    if (l == 0) { zs[wid][0] = bsum; zs[wid][1] = bsq; }
    __syncthreads();
    if (t == 0) {
        float a = 0.f, b = 0.f;
#pragma unroll
        for (int w = 0; w < 8; w++) { a += zs[w][0]; b += zs[w][1]; }
        atomicAdd(&d_zstats[0], a);
        atomicAdd(&d_zstats[1], b);
    }
}

// -------- att = sigmoid(bn(z)) --------
__global__ void att_kernel(const float* __restrict__ gamma_c,
                           const float* __restrict__ beta_c, int Ng) {
    int i = blockIdx.x * blockDim.x + threadIdx.x;
    if (i >= Ng) return;
    float inv = 1.f / (float)Ng;
    float mu = d_zstats[0] * inv;
    float var = d_zstats[1] * inv - mu * mu;
    float rs = rsqrtf(var + EPS);
    float zz = (d_z[i] - mu) * rs * gamma_c[0] + beta_c[0];
    d_att[i] = 1.f / (1.f + expf(-zz));
}

// -------- scatter scalar att into S[Nx][27] (rank-1 factorization) --------
// grid = (ceil(P/256), 27): k from blockIdx.y, no integer division per pair.
__global__ void scatter_kernel(const int* __restrict__ pin,
                               const int* __restrict__ pout, int P) {
    int i = blockIdx.x * blockDim.x + threadIdx.x;
    if (i >= P) return;
    int k = blockIdx.y;
    int e = k * P + i;
    float a = d_att[__ldg(&pin[e])];
    atomicAdd(&d_S[(size_t)__ldg(&pout[e]) * KK + k], a);
}

// -------- out = x * (S @ W_inv + b_inv) --------
__global__ __launch_bounds__(256) void output_kernel(
    const float* __restrict__ x, const float* __restrict__ Winv,
    const float* __restrict__ binv, float* __restrict__ out, int Nx) {
    __shared__ float w[KK][CN];
    __shared__ float bb[CN];
    int t = threadIdx.x;
    for (int i = t; i < KK * CN; i += 256) w[i / CN][i % CN] = Winv[i];
    if (t < CN) bb[t] = binv[t];
    __syncthreads();
    int wid = t >> 5, l = t & 31;
    for (int row = blockIdx.x * 8 + wid; row < Nx; row += gridDim.x * 8) {
        float sval = (l < KK) ? d_S[(size_t)row * KK + l] : 0.f;
        int c = 2 * l;
        float a0 = bb[c], a1 = bb[c + 1];
#pragma unroll
        for (int k = 0; k < KK; k++) {
            float sk = __shfl_sync(0xffffffffu, sval, k);
            float2 wk = *(const float2*)&w[k][c];
            a0 = fmaf(sk, wk.x, a0);
            a1 = fmaf(sk, wk.y, a1);
        }
        float2 xv = *(const float2*)&x[(size_t)row * CS + c];
        float2 o;
        o.x = xv.x * a0;
        o.y = xv.y * a1;
        *(float2*)&out[(size_t)row * CS + c] = o;
    }
}

extern "C" void kernel_launch(void* const* d_in, const int* in_sizes, int n_in,
                              void* d_out, int out_size) {
    const float* g        = (const float*)d_in[0];
    const float* x        = (const float*)d_in[1];
    const int*   down_idx = (const int*)d_in[2];
    const int*   pairs_in = (const int*)d_in[3];
    const int*   pairs_out= (const int*)d_in[4];
    const float* Wg       = (const float*)d_in[5];
    const float* Ws       = (const float*)d_in[6];
    const float* Wc       = (const float*)d_in[7];
    const float* W_inv    = (const float*)d_in[8];
    const float* b_inv    = (const float*)d_in[9];
    const float* gamma_g  = (const float*)d_in[10];
    const float* beta_g   = (const float*)d_in[11];
    const float* gamma_s  = (const float*)d_in[12];
    const float* beta_s   = (const float*)d_in[13];
    const float* gamma_c  = (const float*)d_in[14];
    const float* beta_c   = (const float*)d_in[15];

    int Ng = in_sizes[0] / CG;
    int Nx = in_sizes[1] / CS;
    int KP = in_sizes[3];
    int P  = KP / KK;

    zero_kernel<<<2048, 256>>>(Nx * KK);
    gemm_g_kernel<<<(Ng + 127) / 128, 256>>>(g, Wg, Ng);
    gemm_s_kernel<<<(Ng + 127) / 128, 256>>>(x, down_idx, Ws, Ng);
    fuse_kernel<<<(Ng + 7) / 8, 256>>>(Wc, gamma_g, beta_g, gamma_s, beta_s, Ng);
    att_kernel<<<(Ng + 255) / 256, 256>>>(gamma_c, beta_c, Ng);
    dim3 sgrid((P + 255) / 256, KK);
    scatter_kernel<<<sgrid, 256>>>(pairs_in, pairs_out, P);
    output_kernel<<<(Nx + 7) / 8, 256>>>(x, W_inv, b_inv, (float*)d_out, Nx);
}